// round 2
// baseline (speedup 1.0000x reference)
#include <cuda_runtime.h>
#include <math.h>

#define N_IMG 4
#define HW    48
#define CH    3
#define NPIX  (HW*HW*CH)        // 6912 per image
#define NTOT  (N_IMG*NPIX)      // 27648
#define KSZ   21
#define RAD   10
#define NBINS 256
#define TPTS  513               // table points over [0,1], spacing 1/512
#define TWO_LOG2E 2.8853900817779268f

// ---------------- device scratch (no allocations allowed) ----------------
__device__ float g_taps[3][CH][KSZ];        // [0]=M, [1]=G, [2]=W  (separable 1D taps)
__device__ float g_tmp2[2][NTOT];           // row-pass scratch for M and G
__device__ float g_first[NTOT];             // M(inputs)
__device__ float g_blur[NTOT];              // G(inputs)
__device__ float g_diff[NTOT];              // tanh-mean term
__device__ float g_tmpw[NTOT];              // row-pass scratch for W
__device__ float g_bins_cnt[N_IMG][NBINS];
__device__ float g_bins_bp[N_IMG][NBINS];   // bin mean * 2*log2(e)
__device__ float g_table[N_IMG][TPTS + 7];

// ---------------- 1) separable Gaussian taps ----------------
// Reference: k2d = amp*outer(e,e) normalized to unit L2 energy.
// amp cancels; normalized k2d = outer(f,f) with f = e / ||e||_2.
__global__ void k_taps(const float* __restrict__ gm,
                       const float* __restrict__ gw,
                       const float* __restrict__ gg) {
    int id = threadIdx.x;
    if (id >= 9) return;
    int conv = id / 3, c = id % 3;
    const float* gsrc = (conv == 0) ? gm : ((conv == 1) ? gg : gw);
    double sigma  = 1.0 / (double)gsrc[c];
    double inv2s2 = 1.0 / (2.0 * sigma * sigma);
    double m    = 21.0 / 64.0;                 // KS/(2*FS)
    double step = (21.0 / 32.0) / 20.0;        // linspace(0, KS/FS, KS) spacing
    double e[KSZ];
    double s2 = 0.0;
    for (int t = 0; t < KSZ; t++) {
        double d = (double)t * step - m;
        double v = exp(-d * d * inv2s2);
        e[t] = v;
        s2  += v * v;
    }
    double inv = 1.0 / sqrt(s2);
    for (int t = 0; t < KSZ; t++)
        g_taps[conv][c][t] = (float)(e[t] * inv);
}

// ---------------- 2) row pass (along W) for M and G ----------------
__global__ void k_row_mg(const float* __restrict__ in) {
    int i = blockIdx.x * blockDim.x + threadIdx.x;
    if (i >= 2 * NTOT) return;
    int conv = (i >= NTOT) ? 1 : 0;
    int flat = i - conv * NTOT;
    int c = flat % 3;
    int x = (flat / 3) % HW;
    const float* tp = g_taps[conv][c];
    const float* p  = in + flat;
    float acc = 0.f;
#pragma unroll
    for (int t = 0; t < KSZ; t++) {
        int xx = x + t - RAD;
        if (xx >= 0 && xx < HW)
            acc = fmaf(tp[t], p[(t - RAD) * 3], acc);
    }
    g_tmp2[conv][flat] = acc;
}

// ---------------- 3) col pass (along H) for M and G ----------------
__global__ void k_col_mg() {
    int i = blockIdx.x * blockDim.x + threadIdx.x;
    if (i >= 2 * NTOT) return;
    int conv = (i >= NTOT) ? 1 : 0;
    int flat = i - conv * NTOT;
    int c = flat % 3;
    int y = (flat / (3 * HW)) % HW;
    const float* tp = g_taps[conv][c];
    const float* p  = &g_tmp2[conv][flat];
    float acc = 0.f;
#pragma unroll
    for (int t = 0; t < KSZ; t++) {
        int yy = y + t - RAD;
        if (yy >= 0 && yy < HW)
            acc = fmaf(tp[t], p[(t - RAD) * 3 * HW], acc);
    }
    if (conv == 0) g_first[flat] = acc;
    else           g_blur[flat]  = acc;
}

// ---------------- 4) per-image histogram of blurred values ----------------
__global__ void k_hist() {
    int img = blockIdx.x;
    int tid = threadIdx.x;
    const float* b = g_blur + img * NPIX;

    __shared__ float rmin[256], rmax[256];
    float vmin = 3.4e38f, vmax = -3.4e38f;
    for (int i = tid; i < NPIX; i += 256) {
        float v = b[i];
        vmin = fminf(vmin, v);
        vmax = fmaxf(vmax, v);
    }
    rmin[tid] = vmin; rmax[tid] = vmax;
    __syncthreads();
    for (int s = 128; s > 0; s >>= 1) {
        if (tid < s) {
            rmin[tid] = fminf(rmin[tid], rmin[tid + s]);
            rmax[tid] = fmaxf(rmax[tid], rmax[tid + s]);
        }
        __syncthreads();
    }
    __shared__ int   hcnt[NBINS];
    __shared__ float hsum[NBINS];
    hcnt[tid] = 0; hsum[tid] = 0.f;
    __syncthreads();

    float lo = rmin[0], hi = rmax[0];
    float scale = (float)NBINS / fmaxf(hi - lo, 1e-20f);
    for (int i = tid; i < NPIX; i += 256) {
        float v = b[i];
        int bi = (int)((v - lo) * scale);
        bi = min(bi, NBINS - 1);
        atomicAdd(&hcnt[bi], 1);
        atomicAdd(&hsum[bi], v);
    }
    __syncthreads();

    int   cc   = hcnt[tid];
    float mean = (cc > 0) ? (hsum[tid] / (float)cc)
                          : (lo + ((float)tid + 0.5f) / scale);
    g_bins_cnt[img][tid] = (float)cc;
    g_bins_bp[img][tid]  = mean * TWO_LOG2E;
}

// ---------------- 5) build F(x) table: F = mean_q tanh(x - b_q) ----------------
// grid: N_IMG * 33 blocks, 256 threads = 16 points x 16 partial-sum lanes.
__global__ void k_table() {
    int img   = blockIdx.x / 33;
    int chunk = blockIdx.x % 33;
    int tid   = threadIdx.x;

    __shared__ float scnt[NBINS], sbp[NBINS];
    scnt[tid] = g_bins_cnt[img][tid];
    sbp[tid]  = g_bins_bp[img][tid];
    __syncthreads();

    int p_local = tid >> 4;
    int sub     = tid & 15;
    int pt      = chunk * 16 + p_local;

    float acc = 0.f;
    if (pt < TPTS) {
        float xv = (float)pt * (1.0f / 512.0f);
        float x2 = xv * TWO_LOG2E;
#pragma unroll
        for (int k = 0; k < 16; k++) {
            int bidx = sub + (k << 4);            // conflict-free smem pattern
            float u = x2 - sbp[bidx];
            float t;
            asm("ex2.approx.f32 %0, %1;" : "=f"(t) : "f"(u));   // e^{2(x-b)}
            float th = __fdividef(t - 1.0f, t + 1.0f);           // tanh(x-b)
            acc = fmaf(scnt[bidx], th, acc);
        }
    }
    // reduce partial sums across the 16 lanes of each point
#pragma unroll
    for (int off = 8; off > 0; off >>= 1)
        acc += __shfl_down_sync(0xffffffffu, acc, off, 16);
    if (sub == 0 && pt < TPTS)
        g_table[img][pt] = acc * (1.0f / (float)NPIX);
}

// ---------------- 6) per-pixel lookup: diff = F(x) ----------------
__global__ void k_diff(const float* __restrict__ in) {
    int i = blockIdx.x * blockDim.x + threadIdx.x;
    if (i >= NTOT) return;
    int img = i / NPIX;
    float x = in[i];
    float u = fminf(fmaxf(x * 512.0f, 0.0f), 511.9999f);
    int   i0 = (int)u;
    float f  = u - (float)i0;
    float a  = g_table[img][i0];
    float b  = g_table[img][i0 + 1];
    g_diff[i] = fmaf(f, b - a, a);
}

// ---------------- 7) row pass for W on diff ----------------
__global__ void k_row_w() {
    int flat = blockIdx.x * blockDim.x + threadIdx.x;
    if (flat >= NTOT) return;
    int c = flat % 3;
    int x = (flat / 3) % HW;
    const float* tp = g_taps[2][c];
    const float* p  = &g_diff[flat];
    float acc = 0.f;
#pragma unroll
    for (int t = 0; t < KSZ; t++) {
        int xx = x + t - RAD;
        if (xx >= 0 && xx < HW)
            acc = fmaf(tp[t], p[(t - RAD) * 3], acc);
    }
    g_tmpw[flat] = acc;
}

// ---------------- 8) col pass for W + final combine ----------------
__global__ void k_col_w(float* __restrict__ out) {
    int flat = blockIdx.x * blockDim.x + threadIdx.x;
    if (flat >= NTOT) return;
    int c = flat % 3;
    int y = (flat / (3 * HW)) % HW;
    const float* tp = g_taps[2][c];
    const float* p  = &g_tmpw[flat];
    float acc = 0.f;
#pragma unroll
    for (int t = 0; t < KSZ; t++) {
        int yy = y + t - RAD;
        if (yy >= 0 && yy < HW)
            acc = fmaf(tp[t], p[(t - RAD) * 3 * HW], acc);
    }
    out[flat] = g_first[flat] - acc;   // first_term - L * second_term (L=1)
}

// ---------------- launch ----------------
extern "C" void kernel_launch(void* const* d_in, const int* in_sizes, int n_in,
                              void* d_out, int out_size) {
    const float* inputs = (const float*)d_in[0];
    const float* gm     = (const float*)d_in[1];
    const float* gw     = (const float*)d_in[2];
    const float* gg     = (const float*)d_in[3];
    float* out = (float*)d_out;

    k_taps  <<<1, 32>>>(gm, gw, gg);
    k_row_mg<<<(2 * NTOT + 255) / 256, 256>>>(inputs);
    k_col_mg<<<(2 * NTOT + 255) / 256, 256>>>();
    k_hist  <<<N_IMG, 256>>>();
    k_table <<<N_IMG * 33, 256>>>();
    k_diff  <<<(NTOT + 255) / 256, 256>>>(inputs);
    k_row_w <<<(NTOT + 255) / 256, 256>>>();
    k_col_w <<<(NTOT + 255) / 256, 256>>>(out);
}

// round 3
// speedup vs baseline: 1.1822x; 1.1822x over previous
#include <cuda_runtime.h>
#include <math.h>

#define N_IMG  4
#define HW     48
#define CH     3
#define NPIX   (HW*HW*CH)        // 6912 per image
#define KSZ    21
#define RAD    10
#define NBINS  128
#define TPTS   257               // table over [0,1], spacing 1/256
#define NCOPY  8                 // private histogram copies
#define NCHUNK 7                 // ceil(NPIX/1024)
#define TWO_LOG2E 2.8853900817779268f

// ---------------- device globals (no allocation allowed) ----------------
__device__ float g_first[N_IMG * NPIX];
__device__ float g_bins_cnt[N_IMG][NBINS];
__device__ float g_bins_bp[N_IMG][NBINS];   // bin mean * 2*log2(e)
__device__ float g_table[N_IMG][TPTS + 3];

__device__ __forceinline__ float tanh_sc(float u_scaled) {
    // u_scaled = (x-b) * 2*log2(e);  tanh = (e^{2u}-1)/(e^{2u}+1)
    float t;
    asm("ex2.approx.f32 %0, %1;" : "=f"(t) : "f"(u_scaled));
    return __fdividef(t - 1.0f, t + 1.0f);
}

// Separable normalized taps: k2d = outer(e,e)/sum(e^2) = outer(f,f), f = e/||e||2.
__device__ __forceinline__ void compute_taps(const float* __restrict__ g,
                                             float taps[CH][KSZ], int tid) {
    if (tid < CH * KSZ) {
        int c = tid / KSZ, t = tid % KSZ;
        float sigma  = 1.0f / g[c];
        float inv2s2 = 1.0f / (2.0f * sigma * sigma);
        const float m    = 21.0f / 64.0f;             // KS/(2*FS)
        const float step = (21.0f / 32.0f) / 20.0f;   // linspace spacing
        float s2 = 0.0f, mine = 0.0f;
#pragma unroll
        for (int k = 0; k < KSZ; k++) {
            float d = (float)k * step - m;
            float v = __expf(-d * d * inv2s2);
            if (k == t) mine = v;
            s2 = fmaf(v, v, s2);
        }
        taps[c][t] = mine * rsqrtf(s2);
    }
}

// ================= K1: M & G depthwise conv (+ histogram for G) ==========
// grid = 8: bid>>1 = image, bid&1 = conv (0 -> M via gamma_m, 1 -> G via gamma_g)
__global__ __launch_bounds__(1024, 1)
void k_conv(const float* __restrict__ in,
            const float* __restrict__ gm,
            const float* __restrict__ gg) {
    __shared__ float s_taps[CH][KSZ];
    __shared__ float s_row[NPIX];
    __shared__ float s_hcnt[NCOPY][NBINS];
    __shared__ float s_hsum[NCOPY][NBINS];
    __shared__ float s_red[64];
    __shared__ float s_lo, s_hi;

    int tid  = threadIdx.x;
    int img  = blockIdx.x >> 1;
    int conv = blockIdx.x & 1;
    const float* ip = in + img * NPIX;

    compute_taps(conv ? gg : gm, s_taps, tid);
    __syncthreads();

    // ---- row pass (along W): global -> smem ----
#pragma unroll
    for (int k = 0; k < NCHUNK; k++) {
        int flat = tid + k * 1024;
        if (flat < NPIX) {
            int c = flat % 3;
            int x = (flat / 3) % HW;
            const float* tp = s_taps[c];
            float acc = 0.f;
#pragma unroll
            for (int t = 0; t < KSZ; t++) {
                int xx = x + t - RAD;
                if (xx >= 0 && xx < HW)
                    acc = fmaf(tp[t], ip[flat + (t - RAD) * 3], acc);
            }
            s_row[flat] = acc;
        }
    }
    __syncthreads();

    // ---- col pass (along H): smem -> registers ----
    float bv[NCHUNK];
#pragma unroll
    for (int k = 0; k < NCHUNK; k++) {
        int flat = tid + k * 1024;
        float acc = 0.f;
        if (flat < NPIX) {
            int c = flat % 3;
            int y = flat / (3 * HW);
            const float* tp = s_taps[c];
#pragma unroll
            for (int t = 0; t < KSZ; t++) {
                int yy = y + t - RAD;
                if (yy >= 0 && yy < HW)
                    acc = fmaf(tp[t], s_row[flat + (t - RAD) * 3 * HW], acc);
            }
            if (conv == 0) g_first[img * NPIX + flat] = acc;
        }
        bv[k] = acc;
    }
    if (conv == 0) return;

    // ---- block min/max of blur values ----
    float lo = 3.4e38f, hi = -3.4e38f;
#pragma unroll
    for (int k = 0; k < NCHUNK; k++) {
        int flat = tid + k * 1024;
        if (flat < NPIX) { lo = fminf(lo, bv[k]); hi = fmaxf(hi, bv[k]); }
    }
#pragma unroll
    for (int off = 16; off > 0; off >>= 1) {
        lo = fminf(lo, __shfl_down_sync(0xffffffffu, lo, off));
        hi = fmaxf(hi, __shfl_down_sync(0xffffffffu, hi, off));
    }
    int wid = tid >> 5, lane = tid & 31;
    if (lane == 0) { s_red[wid] = lo; s_red[32 + wid] = hi; }
    // zero histograms while reduction lands
    for (int i = tid; i < NCOPY * NBINS; i += 1024) {
        (&s_hcnt[0][0])[i] = 0.f;
        (&s_hsum[0][0])[i] = 0.f;
    }
    __syncthreads();
    if (tid < 32) {
        float l2 = s_red[tid], h2 = s_red[32 + tid];
#pragma unroll
        for (int off = 16; off > 0; off >>= 1) {
            l2 = fminf(l2, __shfl_down_sync(0xffffffffu, l2, off));
            h2 = fmaxf(h2, __shfl_down_sync(0xffffffffu, h2, off));
        }
        if (tid == 0) { s_lo = l2; s_hi = h2; }
    }
    __syncthreads();

    float blo = s_lo;
    float scale = (float)NBINS / fmaxf(s_hi - blo, 1e-20f);

    // ---- bin into private copy (4 warps per copy) ----
    int hid = wid & (NCOPY - 1);
#pragma unroll
    for (int k = 0; k < NCHUNK; k++) {
        int flat = tid + k * 1024;
        if (flat < NPIX) {
            float v = bv[k];
            int bi = min((int)((v - blo) * scale), NBINS - 1);
            atomicAdd(&s_hcnt[hid][bi], 1.0f);
            atomicAdd(&s_hsum[hid][bi], v);
        }
    }
    __syncthreads();

    // ---- merge copies, write bins ----
    if (tid < NBINS) {
        float cc = 0.f, ss = 0.f;
#pragma unroll
        for (int h = 0; h < NCOPY; h++) { cc += s_hcnt[h][tid]; ss += s_hsum[h][tid]; }
        float mean = (cc > 0.f) ? (ss / cc)
                                : (blo + ((float)tid + 0.5f) / scale);
        g_bins_cnt[img][tid] = cc;
        g_bins_bp[img][tid]  = mean * TWO_LOG2E;
    }
}

// ================= K2: F(x) table, F = mean_q tanh(x - b_q) ==============
// grid = N_IMG*33; each block: 8 warps = 8 points, 32 lanes x 4 bins each.
__global__ void k_table() {
    int img   = blockIdx.x / 33;
    int chunk = blockIdx.x % 33;
    int tid   = threadIdx.x;

    __shared__ float scnt[NBINS], sbp[NBINS];
    if (tid < NBINS) { scnt[tid] = g_bins_cnt[img][tid]; sbp[tid] = g_bins_bp[img][tid]; }
    __syncthreads();

    int lane = tid & 31;
    int pt   = chunk * 8 + (tid >> 5);

    float acc = 0.f;
    if (pt < TPTS) {
        float x2 = (float)pt * (TWO_LOG2E / 256.0f);
#pragma unroll
        for (int k = 0; k < NBINS / 32; k++) {
            int b = lane + (k << 5);
            acc = fmaf(scnt[b], tanh_sc(x2 - sbp[b]), acc);
        }
    }
#pragma unroll
    for (int off = 16; off > 0; off >>= 1)
        acc += __shfl_down_sync(0xffffffffu, acc, off);
    if (lane == 0 && pt < TPTS)
        g_table[img][pt] = acc * (1.0f / (float)NPIX);
}

// ====== K3: diff = F(x) lookup, W conv (row+col), combine with first ======
// grid = N_IMG; dynamic smem: s_diff[NPIX] + s_row[NPIX]
__global__ __launch_bounds__(1024, 1)
void k_final(const float* __restrict__ in,
             const float* __restrict__ gw,
             float* __restrict__ out) {
    extern __shared__ float sm[];
    float* s_diff = sm;
    float* s_row  = sm + NPIX;
    __shared__ float s_taps[CH][KSZ];
    __shared__ float s_tab[TPTS + 1];

    int tid = threadIdx.x;
    int img = blockIdx.x;
    const float* ip = in + img * NPIX;

    compute_taps(gw, s_taps, tid);
    if (tid < TPTS) s_tab[tid] = g_table[img][tid];
    __syncthreads();

    // ---- lookup: diff = F(x) via lerp on 257-pt table ----
#pragma unroll
    for (int k = 0; k < NCHUNK; k++) {
        int flat = tid + k * 1024;
        if (flat < NPIX) {
            float u = fminf(fmaxf(ip[flat] * 256.0f, 0.0f), 255.9999f);
            int   i0 = (int)u;
            float f  = u - (float)i0;
            float a  = s_tab[i0];
            s_diff[flat] = fmaf(f, s_tab[i0 + 1] - a, a);
        }
    }
    __syncthreads();

    // ---- W row pass ----
#pragma unroll
    for (int k = 0; k < NCHUNK; k++) {
        int flat = tid + k * 1024;
        if (flat < NPIX) {
            int c = flat % 3;
            int x = (flat / 3) % HW;
            const float* tp = s_taps[c];
            float acc = 0.f;
#pragma unroll
            for (int t = 0; t < KSZ; t++) {
                int xx = x + t - RAD;
                if (xx >= 0 && xx < HW)
                    acc = fmaf(tp[t], s_diff[flat + (t - RAD) * 3], acc);
            }
            s_row[flat] = acc;
        }
    }
    __syncthreads();

    // ---- W col pass + combine ----
#pragma unroll
    for (int k = 0; k < NCHUNK; k++) {
        int flat = tid + k * 1024;
        if (flat < NPIX) {
            int c = flat % 3;
            int y = flat / (3 * HW);
            const float* tp = s_taps[c];
            float acc = 0.f;
#pragma unroll
            for (int t = 0; t < KSZ; t++) {
                int yy = y + t - RAD;
                if (yy >= 0 && yy < HW)
                    acc = fmaf(tp[t], s_row[flat + (t - RAD) * 3 * HW], acc);
            }
            out[img * NPIX + flat] = g_first[img * NPIX + flat] - acc;  // L = 1
        }
    }
}

// ---------------- launch ----------------
extern "C" void kernel_launch(void* const* d_in, const int* in_sizes, int n_in,
                              void* d_out, int out_size) {
    const float* inputs = (const float*)d_in[0];
    const float* gm     = (const float*)d_in[1];
    const float* gw     = (const float*)d_in[2];
    const float* gg     = (const float*)d_in[3];
    float* out = (float*)d_out;

    static_assert(2 * NPIX * sizeof(float) == 55296, "smem size");
    cudaFuncSetAttribute(k_final, cudaFuncAttributeMaxDynamicSharedMemorySize,
                         2 * NPIX * (int)sizeof(float));

    k_conv <<<2 * N_IMG, 1024>>>(inputs, gm, gg);
    k_table<<<N_IMG * 33, 256>>>();
    k_final<<<N_IMG, 1024, 2 * NPIX * sizeof(float)>>>(inputs, gw, out);
}

// round 4
// speedup vs baseline: 1.8061x; 1.5277x over previous
#include <cuda_runtime.h>
#include <math.h>

#define N_IMG  4
#define HW     48
#define CH     3
#define ROWF   (HW*CH)           // 144 floats per image row
#define NPIX   (HW*ROWF)         // 6912 per image
#define KSZ    21
#define RAD    10
#define NBINS  128
#define TPTS   257               // table over [0,1], spacing 1/256
#define NCOPY  8                 // private histogram copies
#define NSLICE 6                 // row-bands per image
#define ORPS   8                 // output rows per slice
#define HROWS  28                // halo rows per slice (8 + 2*10)
#define PADF   30                // horizontal pad (10 px * 3 ch) each side
#define RS     204               // padded row stride = 30+144+30
#define TWO_LOG2E 2.8853900817779268f

// ---------------- device globals (no allocation allowed) ----------------
__device__ float g_first[N_IMG * NPIX];
__device__ float g_pcnt[N_IMG][NSLICE][NBINS];
__device__ float g_psum[N_IMG][NSLICE][NBINS];
__device__ float g_table[N_IMG][TPTS + 3];
__device__ float g_hi;

__device__ __forceinline__ float tanh_sc(float u_scaled) {
    // u_scaled = (x-b) * 2*log2(e);  tanh = (e^{2u}-1)/(e^{2u}+1)
    float t;
    asm("ex2.approx.f32 %0, %1;" : "=f"(t) : "f"(u_scaled));
    return __fdividef(t - 1.0f, t + 1.0f);
}

// Separable normalized taps: k2d = outer(e,e)/sum(e^2) = outer(f,f), f = e/||e||2.
__device__ __forceinline__ void compute_taps(const float* __restrict__ g,
                                             float taps[CH][KSZ], int tid) {
    if (tid < CH * KSZ) {
        int c = tid / KSZ, t = tid % KSZ;
        float sigma  = 1.0f / g[c];
        float inv2s2 = 1.0f / (2.0f * sigma * sigma);
        const float m    = 21.0f / 64.0f;             // KS/(2*FS)
        const float step = (21.0f / 32.0f) / 20.0f;   // linspace spacing
        float s2 = 0.0f, mine = 0.0f;
#pragma unroll
        for (int k = 0; k < KSZ; k++) {
            float d = (float)k * step - m;
            float v = __expf(-d * d * inv2s2);
            if (k == t) mine = v;
            s2 = fmaf(v, v, s2);
        }
        taps[c][t] = mine * rsqrtf(s2);
    }
}

// ================= K1: M & G depthwise conv slices (+ partial hist for G) =
// grid = N_IMG * 2 * NSLICE = 48.  512 threads.
__global__ __launch_bounds__(512, 1)
void k_conv(const float* __restrict__ in,
            const float* __restrict__ gm,
            const float* __restrict__ gg) {
    __shared__ float s_taps[CH][KSZ];
    __shared__ float s_sum[CH];
    __shared__ float s_in[HROWS * RS];       // zero-padded input halo
    __shared__ float s_row[HROWS * ROWF];    // row-filtered halo
    __shared__ float s_hc[NCOPY][NBINS];
    __shared__ float s_hs[NCOPY][NBINS];

    int tid   = threadIdx.x;
    int b     = blockIdx.x;
    int img   = b / (2 * NSLICE);
    int rem   = b % (2 * NSLICE);
    int conv  = rem / NSLICE;                // 0 = M, 1 = G
    int slice = rem % NSLICE;
    const float* ip = in + img * NPIX;

    compute_taps(conv ? gg : gm, s_taps, tid);
    for (int i = tid; i < HROWS * RS; i += 512) s_in[i] = 0.f;
    {
        float* hc = &s_hc[0][0];
        float* hs = &s_hs[0][0];
        for (int i = tid; i < NCOPY * NBINS; i += 512) { hc[i] = 0.f; hs[i] = 0.f; }
    }
    __syncthreads();

    if (tid < CH) {      // squared tap-sum per channel (analytic blur upper bound)
        float s = 0.f;
#pragma unroll
        for (int t = 0; t < KSZ; t++) s += s_taps[tid][t];
        s_sum[tid] = s * s;
    }

    // ---- fill padded halo ----
    int grow0 = slice * ORPS - RAD;
    for (int i = tid; i < HROWS * ROWF; i += 512) {
        int hr = i / ROWF, off = i - hr * ROWF;
        int grow = grow0 + hr;
        if (grow >= 0 && grow < HW)
            s_in[hr * RS + PADF + off] = ip[grow * ROWF + off];
    }
    __syncthreads();

    float hi    = fmaxf(s_sum[0], fmaxf(s_sum[1], s_sum[2]));
    float scale = (float)NBINS / hi;

    // ---- row pass (along W), branch-free ----
    for (int i = tid; i < HROWS * ROWF; i += 512) {
        int hr = i / ROWF, off = i - hr * ROWF;
        const float* tp = s_taps[off % 3];
        const float* p  = &s_in[hr * RS + PADF + off - RAD * 3];
        float acc = 0.f;
#pragma unroll
        for (int t = 0; t < KSZ; t++) acc = fmaf(tp[t], p[t * 3], acc);
        s_row[i] = acc;
    }
    __syncthreads();

    // ---- col pass (along H), branch-free; write or bin ----
    int hid = (tid >> 6) & (NCOPY - 1);
    for (int i = tid; i < ORPS * ROWF; i += 512) {
        int r = i / ROWF, off = i - r * ROWF;
        const float* tp = s_taps[off % 3];
        const float* p  = &s_row[r * ROWF + off];
        float acc = 0.f;
#pragma unroll
        for (int t = 0; t < KSZ; t++) acc = fmaf(tp[t], p[t * ROWF], acc);
        if (conv == 0) {
            g_first[img * NPIX + (slice * ORPS + r) * ROWF + off] = acc;
        } else {
            int bi = min(max((int)(acc * scale), 0), NBINS - 1);
            atomicAdd(&s_hc[hid][bi], 1.0f);
            atomicAdd(&s_hs[hid][bi], acc);
        }
    }

    if (conv) {
        __syncthreads();
        if (tid < NBINS) {
            float cc = 0.f, ss = 0.f;
#pragma unroll
            for (int h = 0; h < NCOPY; h++) { cc += s_hc[h][tid]; ss += s_hs[h][tid]; }
            g_pcnt[img][slice][tid] = cc;
            g_psum[img][slice][tid] = ss;
        }
        if (tid == 0) g_hi = hi;   // identical value from every G block
    }
}

// ================= K2: F(x) table, F = mean_q tanh(x - b_q) ==============
// grid = N_IMG*33; 256 threads = 8 warps = 8 points, 32 lanes x 4 bins each.
__global__ void k_table() {
    int img   = blockIdx.x / 33;
    int chunk = blockIdx.x % 33;
    int tid   = threadIdx.x;

    __shared__ float scnt[NBINS], sbp[NBINS];
    if (tid < NBINS) {
        float cc = 0.f, ss = 0.f;
#pragma unroll
        for (int s = 0; s < NSLICE; s++) {
            cc += g_pcnt[img][s][tid];
            ss += g_psum[img][s][tid];
        }
        float hi   = g_hi;
        float mean = (cc > 0.f) ? (ss / cc)
                                : ((float)tid + 0.5f) * hi / (float)NBINS;
        scnt[tid] = cc;
        sbp[tid]  = mean * TWO_LOG2E;
    }
    __syncthreads();

    int lane = tid & 31;
    int pt   = chunk * 8 + (tid >> 5);

    float acc = 0.f;
    if (pt < TPTS) {
        float x2 = (float)pt * (TWO_LOG2E / 256.0f);
#pragma unroll
        for (int k = 0; k < NBINS / 32; k++) {
            int bb = lane + (k << 5);
            acc = fmaf(scnt[bb], tanh_sc(x2 - sbp[bb]), acc);
        }
    }
#pragma unroll
    for (int off = 16; off > 0; off >>= 1)
        acc += __shfl_down_sync(0xffffffffu, acc, off);
    if (lane == 0 && pt < TPTS)
        g_table[img][pt] = acc * (1.0f / (float)NPIX);
}

// ====== K3: diff lookup + W conv slice + combine. grid = N_IMG*NSLICE ====
__global__ __launch_bounds__(512, 1)
void k_final(const float* __restrict__ in,
             const float* __restrict__ gw,
             float* __restrict__ out) {
    __shared__ float s_taps[CH][KSZ];
    __shared__ float s_tab[TPTS + 1];
    __shared__ float s_diff[HROWS * RS];     // zero-padded diff halo
    __shared__ float s_row[HROWS * ROWF];

    int tid   = threadIdx.x;
    int img   = blockIdx.x / NSLICE;
    int slice = blockIdx.x % NSLICE;
    const float* ip = in + img * NPIX;

    compute_taps(gw, s_taps, tid);
    if (tid < TPTS) s_tab[tid] = g_table[img][tid];
    for (int i = tid; i < HROWS * RS; i += 512) s_diff[i] = 0.f;
    __syncthreads();

    // ---- diff = F(x) via lerp, into padded halo ----
    int grow0 = slice * ORPS - RAD;
    for (int i = tid; i < HROWS * ROWF; i += 512) {
        int hr = i / ROWF, off = i - hr * ROWF;
        int grow = grow0 + hr;
        if (grow >= 0 && grow < HW) {
            float u  = fminf(fmaxf(ip[grow * ROWF + off] * 256.0f, 0.0f), 255.9999f);
            int   i0 = (int)u;
            float f  = u - (float)i0;
            float a  = s_tab[i0];
            s_diff[hr * RS + PADF + off] = fmaf(f, s_tab[i0 + 1] - a, a);
        }
    }
    __syncthreads();

    // ---- W row pass ----
    for (int i = tid; i < HROWS * ROWF; i += 512) {
        int hr = i / ROWF, off = i - hr * ROWF;
        const float* tp = s_taps[off % 3];
        const float* p  = &s_diff[hr * RS + PADF + off - RAD * 3];
        float acc = 0.f;
#pragma unroll
        for (int t = 0; t < KSZ; t++) acc = fmaf(tp[t], p[t * 3], acc);
        s_row[i] = acc;
    }
    __syncthreads();

    // ---- W col pass + combine ----
    for (int i = tid; i < ORPS * ROWF; i += 512) {
        int r = i / ROWF, off = i - r * ROWF;
        const float* tp = s_taps[off % 3];
        const float* p  = &s_row[r * ROWF + off];
        float acc = 0.f;
#pragma unroll
        for (int t = 0; t < KSZ; t++) acc = fmaf(tp[t], p[t * ROWF], acc);
        int gidx = img * NPIX + (slice * ORPS + r) * ROWF + off;
        out[gidx] = g_first[gidx] - acc;     // first_term - L * second_term (L=1)
    }
}

// ---------------- launch ----------------
extern "C" void kernel_launch(void* const* d_in, const int* in_sizes, int n_in,
                              void* d_out, int out_size) {
    const float* inputs = (const float*)d_in[0];
    const float* gm     = (const float*)d_in[1];
    const float* gw     = (const float*)d_in[2];
    const float* gg     = (const float*)d_in[3];
    float* out = (float*)d_out;

    k_conv <<<N_IMG * 2 * NSLICE, 512>>>(inputs, gm, gg);
    k_table<<<N_IMG * 33, 256>>>();
    k_final<<<N_IMG * NSLICE, 512>>>(inputs, gw, out);
}